// round 1
// baseline (speedup 1.0000x reference)
#include <cuda_runtime.h>
#include <cstdint>

#define BATCH 8
#define SEQ   2048
#define CIN   512
#define DH    64
#define COUT  512
#define MROWS (BATCH*SEQ)   // 16384

// scratch (allocation-free rule: __device__ globals)
__device__ float g_Q[(size_t)MROWS * DH];
__device__ float g_K[(size_t)MROWS * DH];
__device__ float g_V[(size_t)MROWS * COUT];

// ---------------------------------------------------------------------------
// Fused QKV projection: Y[M, 640] = X[M,512] @ [Wq(512x64) | Wk(512x64) | Wv(512x512)]
// 128x128 block tile, Ktile=8, 256 threads, 8x8 microtile.
// ---------------------------------------------------------------------------
__global__ __launch_bounds__(256) void qkv_kernel(
    const float* __restrict__ X,
    const float* __restrict__ Wq,
    const float* __restrict__ Wk,
    const float* __restrict__ Wv)
{
    __shared__ float As[8][128];
    __shared__ float Bs[8][128];

    const int tid = threadIdx.x;
    const int tx = tid & 15;
    const int ty = tid >> 4;
    const int m0 = blockIdx.x * 128;
    const int n0 = blockIdx.y * 128;

    // A load mapping: 2 threads per row, 4 consecutive k each
    const int a_row = tid >> 1;
    const int a_k   = (tid & 1) * 4;
    // B load mapping: 32 threads per k-row, 4 consecutive n each
    const int b_k = tid >> 5;
    const int b_n = (tid & 31) * 4;
    const int ng  = n0 + b_n;

    // per-thread constant source pointer for the B float4 (regions never split a
    // 4-aligned group: boundaries 64 and 128 are multiples of 4)
    const float* bsrc;
    int bld;
    if (ng < 64)       { bsrc = Wq + ng;         bld = 64;  }
    else if (ng < 128) { bsrc = Wk + (ng - 64);  bld = 64;  }
    else               { bsrc = Wv + (ng - 128); bld = 512; }

    float acc[8][8];
#pragma unroll
    for (int i = 0; i < 8; i++)
#pragma unroll
        for (int j = 0; j < 8; j++) acc[i][j] = 0.f;

    for (int k0 = 0; k0 < CIN; k0 += 8) {
        float4 av = *reinterpret_cast<const float4*>(
            &X[(size_t)(m0 + a_row) * CIN + k0 + a_k]);
        As[a_k + 0][a_row] = av.x;
        As[a_k + 1][a_row] = av.y;
        As[a_k + 2][a_row] = av.z;
        As[a_k + 3][a_row] = av.w;
        *reinterpret_cast<float4*>(&Bs[b_k][b_n]) =
            *reinterpret_cast<const float4*>(&bsrc[(size_t)(k0 + b_k) * bld]);
        __syncthreads();

#pragma unroll
        for (int kk = 0; kk < 8; kk++) {
            float4 a0 = *reinterpret_cast<const float4*>(&As[kk][ty * 8]);
            float4 a1 = *reinterpret_cast<const float4*>(&As[kk][ty * 8 + 4]);
            float4 b0 = *reinterpret_cast<const float4*>(&Bs[kk][tx * 8]);
            float4 b1 = *reinterpret_cast<const float4*>(&Bs[kk][tx * 8 + 4]);
            float a[8] = {a0.x, a0.y, a0.z, a0.w, a1.x, a1.y, a1.z, a1.w};
            float b[8] = {b0.x, b0.y, b0.z, b0.w, b1.x, b1.y, b1.z, b1.w};
#pragma unroll
            for (int i = 0; i < 8; i++)
#pragma unroll
                for (int j = 0; j < 8; j++)
                    acc[i][j] += a[i] * b[j];
        }
        __syncthreads();
    }

    // epilogue: route columns to Q / K / V scratch
#pragma unroll
    for (int i = 0; i < 8; i++) {
        const int row = m0 + ty * 8 + i;
#pragma unroll
        for (int j = 0; j < 8; j++) {
            const int n = n0 + tx * 8 + j;
            const float v = acc[i][j];
            if (n < 64)       g_Q[(size_t)row * DH + n] = v;
            else if (n < 128) g_K[(size_t)row * DH + (n - 64)] = v;
            else              g_V[(size_t)row * COUT + (n - 128)] = v;
        }
    }
}

// ---------------------------------------------------------------------------
// Flash attention, fp32. One CTA per (batch, 64-query tile), 512 threads.
// Warp w owns output rows w*4..w*4+3 (full-warp shuffle softmax reductions).
// Per thread: 4 rows x 16 cols of O (cols = lane*4 + q*128 + u).
// smem: Qt[64][68] (K-transposed, pre-scaled), Kt[64][68], Ps[64][68], Vs[64][512]
// ---------------------------------------------------------------------------
#define BM 64
#define BN 64
#define QTILES (SEQ / BM)       // 32
#define QT_STRIDE 68
#define SM_QT 0
#define SM_KT (64 * QT_STRIDE)              // 4352
#define SM_PS (2 * 64 * QT_STRIDE)          // 8704
#define SM_VS (3 * 64 * QT_STRIDE)          // 13056
#define SMEM_FLOATS (3 * 64 * QT_STRIDE + 64 * 512)   // 45824
#define SMEM_BYTES  (SMEM_FLOATS * 4)                 // 183296

__global__ __launch_bounds__(512, 1) void attn_kernel(float* __restrict__ out)
{
    extern __shared__ float sm[];
    float* Qt = sm + SM_QT;
    float* Kt = sm + SM_KT;
    float* Ps = sm + SM_PS;
    float* Vs = sm + SM_VS;

    const int tid  = threadIdx.x;
    const int warp = tid >> 5;
    const int lane = tid & 31;
    const int b    = blockIdx.y;
    const int qt   = (int)gridDim.x - 1 - (int)blockIdx.x;  // heavy tiles first
    const int q0   = qt * BM;
    const int r0   = warp * 4;

    // load Q tile transposed into Qt[d][row], pre-scaled by 1/sqrt(64)
#pragma unroll
    for (int j = 0; j < 2; j++) {
        int id4 = tid + j * 512;        // 1024 float4 total
        int r   = id4 >> 4;             // 16 float4 per row
        int d   = (id4 & 15) * 4;
        float4 v = *reinterpret_cast<const float4*>(
            &g_Q[(size_t)(b * SEQ + q0 + r) * DH + d]);
        Qt[(d + 0) * QT_STRIDE + r] = v.x * 0.125f;
        Qt[(d + 1) * QT_STRIDE + r] = v.y * 0.125f;
        Qt[(d + 2) * QT_STRIDE + r] = v.z * 0.125f;
        Qt[(d + 3) * QT_STRIDE + r] = v.w * 0.125f;
    }

    float O[4][16];
#pragma unroll
    for (int i = 0; i < 4; i++)
#pragma unroll
        for (int c = 0; c < 16; c++) O[i][c] = 0.f;
    float m_i[4], l_i[4];
#pragma unroll
    for (int i = 0; i < 4; i++) { m_i[i] = -1e30f; l_i[i] = 0.f; }

    for (int kt = 0; kt <= qt; kt++) {
        const int k0 = kt * BN;
        // load K tile transposed
#pragma unroll
        for (int j = 0; j < 2; j++) {
            int id4 = tid + j * 512;
            int r   = id4 >> 4;
            int d   = (id4 & 15) * 4;
            float4 v = *reinterpret_cast<const float4*>(
                &g_K[(size_t)(b * SEQ + k0 + r) * DH + d]);
            Kt[(d + 0) * QT_STRIDE + r] = v.x;
            Kt[(d + 1) * QT_STRIDE + r] = v.y;
            Kt[(d + 2) * QT_STRIDE + r] = v.z;
            Kt[(d + 3) * QT_STRIDE + r] = v.w;
        }
        // load V tile [64][512]
#pragma unroll
        for (int j = 0; j < 16; j++) {
            int id4 = tid + j * 512;        // 8192 float4
            int kk  = id4 >> 7;             // 128 float4 per row
            int c   = (id4 & 127) * 4;
            *reinterpret_cast<float4*>(&Vs[kk * 512 + c]) =
                *reinterpret_cast<const float4*>(
                    &g_V[(size_t)(b * SEQ + k0 + kk) * COUT + c]);
        }
        __syncthreads();

        // S = Q K^T  (4 rows x 2 cols per thread; cols = lane*2 + j)
        float s00 = 0.f, s01 = 0.f, s10 = 0.f, s11 = 0.f,
              s20 = 0.f, s21 = 0.f, s30 = 0.f, s31 = 0.f;
#pragma unroll 8
        for (int d = 0; d < DH; d++) {
            float4 a  = *reinterpret_cast<const float4*>(&Qt[d * QT_STRIDE + r0]);
            float2 bb = *reinterpret_cast<const float2*>(&Kt[d * QT_STRIDE + lane * 2]);
            s00 += a.x * bb.x; s01 += a.x * bb.y;
            s10 += a.y * bb.x; s11 += a.y * bb.y;
            s20 += a.z * bb.x; s21 += a.z * bb.y;
            s30 += a.w * bb.x; s31 += a.w * bb.y;
        }
        float s[4][2] = {{s00, s01}, {s10, s11}, {s20, s21}, {s30, s31}};

        // causal mask on the diagonal tile (k0 == q0)
        if (kt == qt) {
            const int c0 = lane * 2;
#pragma unroll
            for (int i = 0; i < 4; i++) {
                if (c0     > r0 + i) s[i][0] = -1e30f;
                if (c0 + 1 > r0 + i) s[i][1] = -1e30f;
            }
        }

        // online softmax per row (rows are warp-local)
#pragma unroll
        for (int i = 0; i < 4; i++) {
            float mx = fmaxf(s[i][0], s[i][1]);
#pragma unroll
            for (int off = 16; off > 0; off >>= 1)
                mx = fmaxf(mx, __shfl_xor_sync(0xffffffffu, mx, off));
            float mn    = fmaxf(m_i[i], mx);
            float alpha = __expf(m_i[i] - mn);
            float p0 = __expf(s[i][0] - mn);
            float p1 = __expf(s[i][1] - mn);
            float rs = p0 + p1;
#pragma unroll
            for (int off = 16; off > 0; off >>= 1)
                rs += __shfl_xor_sync(0xffffffffu, rs, off);
            l_i[i] = l_i[i] * alpha + rs;
            m_i[i] = mn;
            Ps[(r0 + i) * QT_STRIDE + lane * 2]     = p0;
            Ps[(r0 + i) * QT_STRIDE + lane * 2 + 1] = p1;
#pragma unroll
            for (int c = 0; c < 16; c++) O[i][c] *= alpha;
        }
        __syncwarp();   // Ps rows are private to this warp

        // O += P @ V  (cols: lane*4 + q*128 + u)
#pragma unroll 4
        for (int k = 0; k < BN; k++) {
            float4 b0 = *reinterpret_cast<const float4*>(&Vs[k * 512 + lane * 4]);
            float4 b1 = *reinterpret_cast<const float4*>(&Vs[k * 512 + lane * 4 + 128]);
            float4 b2 = *reinterpret_cast<const float4*>(&Vs[k * 512 + lane * 4 + 256]);
            float4 b3 = *reinterpret_cast<const float4*>(&Vs[k * 512 + lane * 4 + 384]);
#pragma unroll
            for (int i = 0; i < 4; i++) {
                float p = Ps[(r0 + i) * QT_STRIDE + k];
                O[i][0]  += p * b0.x; O[i][1]  += p * b0.y;
                O[i][2]  += p * b0.z; O[i][3]  += p * b0.w;
                O[i][4]  += p * b1.x; O[i][5]  += p * b1.y;
                O[i][6]  += p * b1.z; O[i][7]  += p * b1.w;
                O[i][8]  += p * b2.x; O[i][9]  += p * b2.y;
                O[i][10] += p * b2.z; O[i][11] += p * b2.w;
                O[i][12] += p * b3.x; O[i][13] += p * b3.y;
                O[i][14] += p * b3.z; O[i][15] += p * b3.w;
            }
        }
        __syncthreads();   // protect Kt/Vs before next tile's loads
    }

    // epilogue: normalize and store
#pragma unroll
    for (int i = 0; i < 4; i++) {
        const float inv = 1.f / l_i[i];
        const size_t base = (size_t)(b * SEQ + q0 + r0 + i) * COUT;
#pragma unroll
        for (int q = 0; q < 4; q++) {
            float4 v;
            v.x = O[i][q * 4 + 0] * inv;
            v.y = O[i][q * 4 + 1] * inv;
            v.z = O[i][q * 4 + 2] * inv;
            v.w = O[i][q * 4 + 3] * inv;
            *reinterpret_cast<float4*>(&out[base + lane * 4 + q * 128]) = v;
        }
    }
}

// ---------------------------------------------------------------------------
extern "C" void kernel_launch(void* const* d_in, const int* in_sizes, int n_in,
                              void* d_out, int out_size)
{
    const float* x  = (const float*)d_in[0];
    const float* Wq = (const float*)d_in[1];
    const float* Wk = (const float*)d_in[2];
    const float* Wv = (const float*)d_in[3];
    float* out = (float*)d_out;

    dim3 g1(MROWS / 128, (64 + 64 + COUT) / 128);   // 128 x 5
    qkv_kernel<<<g1, 256>>>(x, Wq, Wk, Wv);

    cudaFuncSetAttribute(attn_kernel,
                         cudaFuncAttributeMaxDynamicSharedMemorySize, SMEM_BYTES);
    attn_kernel<<<dim3(QTILES, BATCH), 512, SMEM_BYTES>>>(out);
}

// round 2
// speedup vs baseline: 1.0002x; 1.0002x over previous
#include <cuda_runtime.h>
#include <cstdint>

#define BATCH 8
#define SEQ   2048
#define CIN   512
#define DH    64
#define COUT  512
#define MROWS (BATCH*SEQ)   // 16384

// scratch (allocation-free rule: __device__ globals)
__device__ float g_Q[(size_t)MROWS * DH];
__device__ float g_K[(size_t)MROWS * DH];
__device__ float g_V[(size_t)MROWS * COUT];

// ---------------------------------------------------------------------------
// Fused QKV projection: Y[M, 640] = X[M,512] @ [Wq(512x64) | Wk(512x64) | Wv(512x512)]
// 128x128 block tile, Ktile=8, 256 threads, 8x8 microtile.
// ---------------------------------------------------------------------------
__global__ __launch_bounds__(256) void qkv_kernel(
    const float* __restrict__ X,
    const float* __restrict__ Wq,
    const float* __restrict__ Wk,
    const float* __restrict__ Wv)
{
    __shared__ float As[8][128];
    __shared__ float Bs[8][128];

    const int tid = threadIdx.x;
    const int tx = tid & 15;
    const int ty = tid >> 4;
    const int m0 = blockIdx.x * 128;
    const int n0 = blockIdx.y * 128;

    // A load mapping: 2 threads per row, 4 consecutive k each
    const int a_row = tid >> 1;
    const int a_k   = (tid & 1) * 4;
    // B load mapping: 32 threads per k-row, 4 consecutive n each
    const int b_k = tid >> 5;
    const int b_n = (tid & 31) * 4;
    const int ng  = n0 + b_n;

    // per-thread constant source pointer for the B float4 (regions never split a
    // 4-aligned group: boundaries 64 and 128 are multiples of 4)
    const float* bsrc;
    int bld;
    if (ng < 64)       { bsrc = Wq + ng;         bld = 64;  }
    else if (ng < 128) { bsrc = Wk + (ng - 64);  bld = 64;  }
    else               { bsrc = Wv + (ng - 128); bld = 512; }

    float acc[8][8];
#pragma unroll
    for (int i = 0; i < 8; i++)
#pragma unroll
        for (int j = 0; j < 8; j++) acc[i][j] = 0.f;

    for (int k0 = 0; k0 < CIN; k0 += 8) {
        float4 av = *reinterpret_cast<const float4*>(
            &X[(size_t)(m0 + a_row) * CIN + k0 + a_k]);
        As[a_k + 0][a_row] = av.x;
        As[a_k + 1][a_row] = av.y;
        As[a_k + 2][a_row] = av.z;
        As[a_k + 3][a_row] = av.w;
        *reinterpret_cast<float4*>(&Bs[b_k][b_n]) =
            *reinterpret_cast<const float4*>(&bsrc[(size_t)(k0 + b_k) * bld]);
        __syncthreads();

#pragma unroll
        for (int kk = 0; kk < 8; kk++) {
            float4 a0 = *reinterpret_cast<const float4*>(&As[kk][ty * 8]);
            float4 a1 = *reinterpret_cast<const float4*>(&As[kk][ty * 8 + 4]);
            float4 b0 = *reinterpret_cast<const float4*>(&Bs[kk][tx * 8]);
            float4 b1 = *reinterpret_cast<const float4*>(&Bs[kk][tx * 8 + 4]);
            float a[8] = {a0.x, a0.y, a0.z, a0.w, a1.x, a1.y, a1.z, a1.w};
            float b[8] = {b0.x, b0.y, b0.z, b0.w, b1.x, b1.y, b1.z, b1.w};
#pragma unroll
            for (int i = 0; i < 8; i++)
#pragma unroll
                for (int j = 0; j < 8; j++)
                    acc[i][j] += a[i] * b[j];
        }
        __syncthreads();
    }

    // epilogue: route columns to Q / K / V scratch
#pragma unroll
    for (int i = 0; i < 8; i++) {
        const int row = m0 + ty * 8 + i;
#pragma unroll
        for (int j = 0; j < 8; j++) {
            const int n = n0 + tx * 8 + j;
            const float v = acc[i][j];
            if (n < 64)       g_Q[(size_t)row * DH + n] = v;
            else if (n < 128) g_K[(size_t)row * DH + (n - 64)] = v;
            else              g_V[(size_t)row * COUT + (n - 128)] = v;
        }
    }
}

// ---------------------------------------------------------------------------
// Flash attention, fp32. One CTA per (batch, 64-query tile), 512 threads.
// Warp w owns output rows w*4..w*4+3 (full-warp shuffle softmax reductions).
// Per thread: 4 rows x 16 cols of O (cols = lane*4 + q*128 + u).
// smem: Qt[64][68] (K-transposed, pre-scaled), Kt[64][68], Ps[64][68], Vs[64][512]
// ---------------------------------------------------------------------------
#define BM 64
#define BN 64
#define QTILES (SEQ / BM)       // 32
#define QT_STRIDE 68
#define SM_QT 0
#define SM_KT (64 * QT_STRIDE)              // 4352
#define SM_PS (2 * 64 * QT_STRIDE)          // 8704
#define SM_VS (3 * 64 * QT_STRIDE)          // 13056
#define SMEM_FLOATS (3 * 64 * QT_STRIDE + 64 * 512)   // 45824
#define SMEM_BYTES  (SMEM_FLOATS * 4)                 // 183296

__global__ __launch_bounds__(512, 1) void attn_kernel(float* __restrict__ out)
{
    extern __shared__ float sm[];
    float* Qt = sm + SM_QT;
    float* Kt = sm + SM_KT;
    float* Ps = sm + SM_PS;
    float* Vs = sm + SM_VS;

    const int tid  = threadIdx.x;
    const int warp = tid >> 5;
    const int lane = tid & 31;
    const int b    = blockIdx.y;
    const int qt   = (int)gridDim.x - 1 - (int)blockIdx.x;  // heavy tiles first
    const int q0   = qt * BM;
    const int r0   = warp * 4;

    // load Q tile transposed into Qt[d][row], pre-scaled by 1/sqrt(64)
#pragma unroll
    for (int j = 0; j < 2; j++) {
        int id4 = tid + j * 512;        // 1024 float4 total
        int r   = id4 >> 4;             // 16 float4 per row
        int d   = (id4 & 15) * 4;
        float4 v = *reinterpret_cast<const float4*>(
            &g_Q[(size_t)(b * SEQ + q0 + r) * DH + d]);
        Qt[(d + 0) * QT_STRIDE + r] = v.x * 0.125f;
        Qt[(d + 1) * QT_STRIDE + r] = v.y * 0.125f;
        Qt[(d + 2) * QT_STRIDE + r] = v.z * 0.125f;
        Qt[(d + 3) * QT_STRIDE + r] = v.w * 0.125f;
    }

    float O[4][16];
#pragma unroll
    for (int i = 0; i < 4; i++)
#pragma unroll
        for (int c = 0; c < 16; c++) O[i][c] = 0.f;
    float m_i[4], l_i[4];
#pragma unroll
    for (int i = 0; i < 4; i++) { m_i[i] = -1e30f; l_i[i] = 0.f; }

    for (int kt = 0; kt <= qt; kt++) {
        const int k0 = kt * BN;
        // load K tile transposed
#pragma unroll
        for (int j = 0; j < 2; j++) {
            int id4 = tid + j * 512;
            int r   = id4 >> 4;
            int d   = (id4 & 15) * 4;
            float4 v = *reinterpret_cast<const float4*>(
                &g_K[(size_t)(b * SEQ + k0 + r) * DH + d]);
            Kt[(d + 0) * QT_STRIDE + r] = v.x;
            Kt[(d + 1) * QT_STRIDE + r] = v.y;
            Kt[(d + 2) * QT_STRIDE + r] = v.z;
            Kt[(d + 3) * QT_STRIDE + r] = v.w;
        }
        // load V tile [64][512]
#pragma unroll
        for (int j = 0; j < 16; j++) {
            int id4 = tid + j * 512;        // 8192 float4
            int kk  = id4 >> 7;             // 128 float4 per row
            int c   = (id4 & 127) * 4;
            *reinterpret_cast<float4*>(&Vs[kk * 512 + c]) =
                *reinterpret_cast<const float4*>(
                    &g_V[(size_t)(b * SEQ + k0 + kk) * COUT + c]);
        }
        __syncthreads();

        // S = Q K^T  (4 rows x 2 cols per thread; cols = lane*2 + j)
        float s00 = 0.f, s01 = 0.f, s10 = 0.f, s11 = 0.f,
              s20 = 0.f, s21 = 0.f, s30 = 0.f, s31 = 0.f;
#pragma unroll 8
        for (int d = 0; d < DH; d++) {
            float4 a  = *reinterpret_cast<const float4*>(&Qt[d * QT_STRIDE + r0]);
            float2 bb = *reinterpret_cast<const float2*>(&Kt[d * QT_STRIDE + lane * 2]);
            s00 += a.x * bb.x; s01 += a.x * bb.y;
            s10 += a.y * bb.x; s11 += a.y * bb.y;
            s20 += a.z * bb.x; s21 += a.z * bb.y;
            s30 += a.w * bb.x; s31 += a.w * bb.y;
        }
        float s[4][2] = {{s00, s01}, {s10, s11}, {s20, s21}, {s30, s31}};

        // causal mask on the diagonal tile (k0 == q0)
        if (kt == qt) {
            const int c0 = lane * 2;
#pragma unroll
            for (int i = 0; i < 4; i++) {
                if (c0     > r0 + i) s[i][0] = -1e30f;
                if (c0 + 1 > r0 + i) s[i][1] = -1e30f;
            }
        }

        // online softmax per row (rows are warp-local)
#pragma unroll
        for (int i = 0; i < 4; i++) {
            float mx = fmaxf(s[i][0], s[i][1]);
#pragma unroll
            for (int off = 16; off > 0; off >>= 1)
                mx = fmaxf(mx, __shfl_xor_sync(0xffffffffu, mx, off));
            float mn    = fmaxf(m_i[i], mx);
            float alpha = __expf(m_i[i] - mn);
            float p0 = __expf(s[i][0] - mn);
            float p1 = __expf(s[i][1] - mn);
            float rs = p0 + p1;
#pragma unroll
            for (int off = 16; off > 0; off >>= 1)
                rs += __shfl_xor_sync(0xffffffffu, rs, off);
            l_i[i] = l_i[i] * alpha + rs;
            m_i[i] = mn;
            Ps[(r0 + i) * QT_STRIDE + lane * 2]     = p0;
            Ps[(r0 + i) * QT_STRIDE + lane * 2 + 1] = p1;
#pragma unroll
            for (int c = 0; c < 16; c++) O[i][c] *= alpha;
        }
        __syncwarp();   // Ps rows are private to this warp

        // O += P @ V  (cols: lane*4 + q*128 + u)
#pragma unroll 4
        for (int k = 0; k < BN; k++) {
            float4 b0 = *reinterpret_cast<const float4*>(&Vs[k * 512 + lane * 4]);
            float4 b1 = *reinterpret_cast<const float4*>(&Vs[k * 512 + lane * 4 + 128]);
            float4 b2 = *reinterpret_cast<const float4*>(&Vs[k * 512 + lane * 4 + 256]);
            float4 b3 = *reinterpret_cast<const float4*>(&Vs[k * 512 + lane * 4 + 384]);
#pragma unroll
            for (int i = 0; i < 4; i++) {
                float p = Ps[(r0 + i) * QT_STRIDE + k];
                O[i][0]  += p * b0.x; O[i][1]  += p * b0.y;
                O[i][2]  += p * b0.z; O[i][3]  += p * b0.w;
                O[i][4]  += p * b1.x; O[i][5]  += p * b1.y;
                O[i][6]  += p * b1.z; O[i][7]  += p * b1.w;
                O[i][8]  += p * b2.x; O[i][9]  += p * b2.y;
                O[i][10] += p * b2.z; O[i][11] += p * b2.w;
                O[i][12] += p * b3.x; O[i][13] += p * b3.y;
                O[i][14] += p * b3.z; O[i][15] += p * b3.w;
            }
        }
        __syncthreads();   // protect Kt/Vs before next tile's loads
    }

    // epilogue: normalize and store
#pragma unroll
    for (int i = 0; i < 4; i++) {
        const float inv = 1.f / l_i[i];
        const size_t base = (size_t)(b * SEQ + q0 + r0 + i) * COUT;
#pragma unroll
        for (int q = 0; q < 4; q++) {
            float4 v;
            v.x = O[i][q * 4 + 0] * inv;
            v.y = O[i][q * 4 + 1] * inv;
            v.z = O[i][q * 4 + 2] * inv;
            v.w = O[i][q * 4 + 3] * inv;
            *reinterpret_cast<float4*>(&out[base + lane * 4 + q * 128]) = v;
        }
    }
}

// ---------------------------------------------------------------------------
extern "C" void kernel_launch(void* const* d_in, const int* in_sizes, int n_in,
                              void* d_out, int out_size)
{
    const float* x  = (const float*)d_in[0];
    const float* Wq = (const float*)d_in[1];
    const float* Wk = (const float*)d_in[2];
    const float* Wv = (const float*)d_in[3];
    float* out = (float*)d_out;

    dim3 g1(MROWS / 128, (64 + 64 + COUT) / 128);   // 128 x 5
    qkv_kernel<<<g1, 256>>>(x, Wq, Wk, Wv);

    cudaFuncSetAttribute(attn_kernel,
                         cudaFuncAttributeMaxDynamicSharedMemorySize, SMEM_BYTES);
    attn_kernel<<<dim3(QTILES, BATCH), 512, SMEM_BYTES>>>(out);
}